// round 3
// baseline (speedup 1.0000x reference)
#include <cuda_runtime.h>
#include <math.h>

// Problem constants (fixed by the reference setup)
#define NFRAG     131072
#define NCELLS    200
#define NGENES_MB 500
#define NSEG      (NCELLS * NGENES_MB)   // 100000
#define NFREQ     50
#define ENC       200                    // 4 * NFREQ
#define EDIM      10
#define CPB       100                    // cells per block (2 blocks per gene)
#define NT        128                    // threads per block
#define MAXF      256                    // max fragments per (gene, 100-cell) block (mean ~131)

typedef unsigned long long u64;

// Scratch (no cudaMalloc allowed)
__device__ int   g_seg_start[NSEG + 1];
__device__ float g_freqs[NFREQ];

// ---------------------------------------------------------------------------
// f32x2 packed helpers (sm_103a FMA pipe, 2 FLOPs/instr)
// ---------------------------------------------------------------------------
__device__ __forceinline__ u64 pk2(float a, float b) {
    u64 d; asm("mov.b64 %0,{%1,%2};" : "=l"(d) : "f"(a), "f"(b)); return d;
}
__device__ __forceinline__ u64 bc2(float a) {
    u64 d; asm("mov.b64 %0,{%1,%1};" : "=l"(d) : "f"(a)); return d;
}
__device__ __forceinline__ u64 fma2(u64 a, u64 b, u64 c) {
    u64 d; asm("fma.rn.f32x2 %0,%1,%2,%3;" : "=l"(d) : "l"(a), "l"(b), "l"(c)); return d;
}
__device__ __forceinline__ u64 mul2(u64 a, u64 b) {
    u64 d; asm("mul.rn.f32x2 %0,%1,%2;" : "=l"(d) : "l"(a), "l"(b)); return d;
}
__device__ __forceinline__ u64 add2(u64 a, u64 b) {
    u64 d; asm("add.rn.f32x2 %0,%1,%2;" : "=l"(d) : "l"(a), "l"(b)); return d;
}
__device__ __forceinline__ float lo2(u64 a) { return __uint_as_float((unsigned)a); }
__device__ __forceinline__ float hi2(u64 a) { return __uint_as_float((unsigned)(a >> 32)); }

// Quadrant fixup: k holds the float BITS of (q + 1.5*2^23); low 2 bits == q&3.
__device__ __forceinline__ float quad_s(unsigned k, float sr, float cr) {
    unsigned b = (k & 1u) ? __float_as_uint(cr) : __float_as_uint(sr);
    return __uint_as_float(b ^ ((k & 2u) << 30));
}
__device__ __forceinline__ float quad_c(unsigned k, float sr, float cr) {
    unsigned b = (k & 1u) ? __float_as_uint(sr) : __float_as_uint(cr);
    return __uint_as_float(b ^ (((k + 1u) & 2u) << 30));
}

// One encoding row (10 weights, 16B-aligned, broadcast LDS) into 5 packed accs
__device__ __forceinline__ void dot_row(const float* __restrict__ rp, float v,
                                        u64& h0, u64& h1, u64& h2, u64& h3, u64& h4) {
    const u64 vv = bc2(v);
    ulonglong2 ab = *(const ulonglong2*)rp;
    ulonglong2 cd = *(const ulonglong2*)(rp + 4);
    u64 e4 = *(const u64*)(rp + 8);
    h0 = fma2(vv, ab.x, h0); h1 = fma2(vv, ab.y, h1);
    h2 = fma2(vv, cd.x, h2); h3 = fma2(vv, cd.y, h3);
    h4 = fma2(vv, e4, h4);
}

// ---------------------------------------------------------------------------
// Kernel 1: segment boundaries via neighbor-diff scatter + exact f32 freqs
// ---------------------------------------------------------------------------
__global__ void seg_scatter_kernel(const int* __restrict__ ix) {
    int f = blockIdx.x * blockDim.x + threadIdx.x;
    if (f < NFREQ) {
        double e = (2.0 * (double)(f + 1)) / (double)NFREQ;
        g_freqs[f] = (float)(1.0 / pow(1000.0, e));
    }
    if (f >= NFRAG) return;
    int cur  = ix[f];
    int prev = (f == 0) ? -1 : ix[f - 1];
    for (int s = prev + 1; s <= cur; ++s) g_seg_start[s] = f;
    if (f == NFRAG - 1)
        for (int s = cur + 1; s <= NSEG; ++s) g_seg_start[s] = NFRAG;
}

// ---------------------------------------------------------------------------
// Kernel 2: one block per (gene slot, 100-cell half). grid = 1000, 128 thr.
//   - stage W1[gene] in SMEM, interleaved per-freq chunks of 4 padded rows
//   - gather the half's fragments via deterministic block scan
//   - per fragment: packed f32x2 sincos + vectorized 200x10 dot + sigmoid
//   - per-cell ordered reduction -> out[c, g]  (no atomics, deterministic)
// ---------------------------------------------------------------------------
__global__ __launch_bounds__(NT, 6) void frag_gene_kernel(
    const float2* __restrict__ coords,
    const int*    __restrict__ genes_oi,
    const float*  __restrict__ W1,
    const float*  __restrict__ b1,
    const float*  __restrict__ w2,
    const float*  __restrict__ b2,
    float*        __restrict__ out)
{
    // per-freq chunk: rows [2j, 2j+1, 100+2j, 101+2j], each padded to 12 floats
    __shared__ __align__(16) float Wsh[NFREQ * 48];   // 9600 B
    __shared__ __align__(16) float b1sh[12], w2sh[12];
    __shared__ float frsh[NFREQ];
    __shared__ int   list[MAXF];
    __shared__ float svals[MAXF];
    __shared__ int   cntarr[NT];
    __shared__ int   starts[NT];

    const int bid  = blockIdx.x;
    const int g    = bid >> 1;                 // gene slot
    const int cellbase = (bid & 1) * CPB;      // 0 or 100
    const int t    = threadIdx.x;
    const int gene = genes_oi[g];

    // Stage per-gene parameters (interleaved chunk layout)
    const float* Wg = W1 + (size_t)gene * (ENC * EDIM);
    for (int i = t; i < ENC * EDIM; i += NT) {
        int e = i / EDIM, o = i - e * EDIM;
        int j, slot;
        if (e < 100) { j = e >> 1; slot = e & 1; }
        else         { int e2 = e - 100; j = e2 >> 1; slot = 2 + (e2 & 1); }
        Wsh[j * 48 + slot * 12 + o] = Wg[i];
    }
    if (t < EDIM)  { b1sh[t] = b1[gene * EDIM + t]; w2sh[t] = w2[gene * EDIM + t]; }
    if (t < NFREQ) { frsh[t] = g_freqs[t]; }

    // Per-cell segment range (thread t <-> cell cellbase+t, t < CPB)
    int a = 0, b = 0;
    if (t < CPB) {
        int s = (cellbase + t) * NGENES_MB + g;
        a = g_seg_start[s];
        b = g_seg_start[s + 1];
    }
    int mycnt = b - a;
    cntarr[t] = mycnt;
    __syncthreads();

    // Inclusive Hillis-Steele scan (128 wide) -> deterministic placement
    #pragma unroll
    for (int off = 1; off < NT; off <<= 1) {
        int v = cntarr[t];
        int add = (t >= off) ? cntarr[t - off] : 0;
        __syncthreads();
        cntarr[t] = v + add;
        __syncthreads();
    }
    int total = cntarr[NT - 1];
    int mystart = cntarr[t] - mycnt;
    starts[t] = mystart;
    for (int i = 0; i < mycnt; i++) {
        int pos = mystart + i;
        if (pos < MAXF) list[pos] = a + i;
    }
    __syncthreads();
    if (total > MAXF) total = MAXF;   // statistically unreachable guard

    // Packed constants (uniform; candidates for UR promotion)
    const u64 INV2   = bc2(0.63661977236758134f);        // 2/pi
    const u64 MAG2   = bc2(12582912.0f);                 // 1.5 * 2^23
    const u64 NMAG2  = bc2(-12582912.0f);
    const u64 NH2    = bc2(-1.57079637050628662109375f); // -pi/2 hi
    const u64 PLO2   = bc2(4.37113900018624283e-8f);     // pi/2 lo correction
    const u64 KS1    = bc2(-1.9515295891e-4f);
    const u64 KS2    = bc2(8.3321608736e-3f);
    const u64 KS3    = bc2(-1.6666654611e-1f);
    const u64 KC1    = bc2(2.443315711809948e-5f);
    const u64 KC2    = bc2(-1.388731625493765e-3f);
    const u64 KC3    = bc2(4.166664568298827e-2f);
    const u64 NHALF2 = bc2(-0.5f);
    const u64 ONE2v  = bc2(1.0f);

    float w2r[EDIM];
    #pragma unroll
    for (int o = 0; o < EDIM; o++) w2r[o] = w2sh[o];
    const u64 B0 = pk2(b1sh[0], b1sh[1]);
    const u64 B1 = pk2(b1sh[2], b1sh[3]);
    const u64 B2 = pk2(b1sh[4], b1sh[5]);
    const u64 B3 = pk2(b1sh[6], b1sh[7]);
    const u64 B4 = pk2(b1sh[8], b1sh[9]);

    // Main per-fragment compute (~1.02 fragments per thread)
    for (int idx = t; idx < total; idx += NT) {
        const int f = list[idx];
        const float2 xy = coords[f];
        const u64 xy2 = pk2(xy.x, xy.y);

        u64 h0 = B0, h1 = B1, h2a = B2, h3 = B3, h4 = B4;

        #pragma unroll 2
        for (int j = 0; j < NFREQ; j++) {
            const u64 t2 = mul2(xy2, bc2(frsh[j]));

            // packed sincos (both coordinates at once)
            u64 qb = fma2(t2, INV2, MAG2);
            unsigned k0 = (unsigned)qb, k1 = (unsigned)(qb >> 32);
            u64 q  = add2(qb, NMAG2);
            u64 r  = fma2(q, NH2, t2);
            r      = fma2(q, PLO2, r);
            u64 s2 = mul2(r, r);
            u64 ps = fma2(s2, KS1, KS2);
            ps     = fma2(ps, s2, KS3);
            u64 sr = fma2(ps, mul2(s2, r), r);
            u64 pc = fma2(s2, KC1, KC2);
            pc     = fma2(pc, s2, KC3);
            pc     = fma2(pc, s2, NHALF2);
            u64 cr = fma2(pc, s2, ONE2v);
            float srl = lo2(sr), srh = hi2(sr), crl = lo2(cr), crh = hi2(cr);

            const float* ch = &Wsh[j * 48];
            dot_row(ch,      quad_s(k0, srl, crl), h0, h1, h2a, h3, h4);
            dot_row(ch + 12, quad_c(k0, srl, crl), h0, h1, h2a, h3, h4);
            dot_row(ch + 24, quad_s(k1, srh, crh), h0, h1, h2a, h3, h4);
            dot_row(ch + 36, quad_c(k1, srh, crh), h0, h1, h2a, h3, h4);
        }

        // sigmoid + per-gene readout weights
        float hv[EDIM] = { lo2(h0), hi2(h0), lo2(h1), hi2(h1), lo2(h2a),
                           hi2(h2a), lo2(h3), hi2(h3), lo2(h4), hi2(h4) };
        float s = 0.0f;
        #pragma unroll
        for (int o = 0; o < EDIM; o++) {
            float sig = __fdividef(1.0f, 1.0f + __expf(-hv[o]));
            s = fmaf(w2r[o], sig, s);
        }
        svals[idx] = s;
    }
    __syncthreads();

    // Deterministic per-cell reduction (cell's fragments are contiguous)
    if (t < CPB) {
        float acc = b2[gene];
        int st = starts[t];
        for (int i = 0; i < mycnt; i++) {
            int pos = st + i;
            if (pos < MAXF) acc += svals[pos];
        }
        out[(cellbase + t) * NGENES_MB + g] = acc;
    }
}

// ---------------------------------------------------------------------------
// Launch
// Inputs (metadata order): 0 coordinates[F,2] f32, 1 genemapping i32 (unused),
// 2 local_cellxgene_ix i32, 3 genes_oi i32, 4 W1[2000,200,10] f32,
// 5 b1[2000,10] f32, 6 w2[2000,10] f32, 7 b2[2000] f32, (8,9 scalars)
// ---------------------------------------------------------------------------
extern "C" void kernel_launch(void* const* d_in, const int* in_sizes, int n_in,
                              void* d_out, int out_size) {
    const float2* coords   = (const float2*)d_in[0];
    const int*    ix       = (const int*)d_in[2];
    const int*    genes_oi = (const int*)d_in[3];
    const float*  W1       = (const float*)d_in[4];
    const float*  b1       = (const float*)d_in[5];
    const float*  w2       = (const float*)d_in[6];
    const float*  b2       = (const float*)d_in[7];
    float*        out      = (float*)d_out;

    seg_scatter_kernel<<<(NFRAG + 255) / 256, 256>>>(ix);
    frag_gene_kernel<<<NGENES_MB * 2, NT>>>(coords, genes_oi, W1, b1, w2, b2, out);
}

// round 5
// speedup vs baseline: 1.0665x; 1.0665x over previous
#include <cuda_runtime.h>
#include <math.h>

// Problem constants (fixed by the reference setup)
#define NFRAG     131072
#define NCELLS    200
#define NGENES_MB 500
#define NSEG      (NCELLS * NGENES_MB)   // 100000
#define NFREQ     50
#define ENC       200                    // 4 * NFREQ
#define EDIM      10
#define NT        128                    // threads per block
#define MAXF      512                    // max fragments per gene (mean ~262, sd ~16)

typedef unsigned long long u64;

// Scratch (no cudaMalloc allowed)
__device__ int   g_seg_start[NSEG + 1];
__device__ float g_freqs[NFREQ];

// ---------------------------------------------------------------------------
// f32x2 packed helpers (sm_103a FMA pipe, 2 FLOPs/instr)
// ---------------------------------------------------------------------------
__device__ __forceinline__ u64 pk2(float a, float b) {
    u64 d; asm("mov.b64 %0,{%1,%2};" : "=l"(d) : "f"(a), "f"(b)); return d;
}
__device__ __forceinline__ u64 bc2(float a) {
    u64 d; asm("mov.b64 %0,{%1,%1};" : "=l"(d) : "f"(a)); return d;
}
__device__ __forceinline__ u64 fma2(u64 a, u64 b, u64 c) {
    u64 d; asm("fma.rn.f32x2 %0,%1,%2,%3;" : "=l"(d) : "l"(a), "l"(b), "l"(c)); return d;
}
__device__ __forceinline__ u64 mul2(u64 a, u64 b) {
    u64 d; asm("mul.rn.f32x2 %0,%1,%2;" : "=l"(d) : "l"(a), "l"(b)); return d;
}
__device__ __forceinline__ u64 add2(u64 a, u64 b) {
    u64 d; asm("add.rn.f32x2 %0,%1,%2;" : "=l"(d) : "l"(a), "l"(b)); return d;
}
__device__ __forceinline__ float lo2(u64 a) { return __uint_as_float((unsigned)a); }
__device__ __forceinline__ float hi2(u64 a) { return __uint_as_float((unsigned)(a >> 32)); }

// Quadrant fixup: k holds float BITS of (q + 1.5*2^23); low 2 bits == q&3.
__device__ __forceinline__ float quad_s(unsigned k, float sr, float cr) {
    unsigned b = (k & 1u) ? __float_as_uint(cr) : __float_as_uint(sr);
    return __uint_as_float(b ^ ((k & 2u) << 30));
}
__device__ __forceinline__ float quad_c(unsigned k, float sr, float cr) {
    unsigned b = (k & 1u) ? __float_as_uint(sr) : __float_as_uint(cr);
    return __uint_as_float(b ^ (((k + 1u) & 2u) << 30));
}

// Packed sincos: Cody-Waite pi/2 reduction + Cephes minimax polys on the
// FMA pipe (proven in R2/R3: rel_err 1.4e-6). v[0]=sin lo, v[1]=cos lo,
// v[2]=sin hi, v[3]=cos hi.
__device__ __forceinline__ void sincos2(u64 t2, float* v) {
    const u64 INV2   = bc2(0.63661977236758134f);        // 2/pi
    const u64 MAG2   = bc2(12582912.0f);                 // 1.5 * 2^23
    const u64 NMAG2  = bc2(-12582912.0f);
    const u64 NH2    = bc2(-1.57079637050628662109375f); // -pi/2 hi
    const u64 PLO2   = bc2(4.37113900018624283e-8f);     // pi/2 lo correction
    const u64 KS1    = bc2(-1.9515295891e-4f);
    const u64 KS2    = bc2(8.3321608736e-3f);
    const u64 KS3    = bc2(-1.6666654611e-1f);
    const u64 KC1    = bc2(2.443315711809948e-5f);
    const u64 KC2    = bc2(-1.388731625493765e-3f);
    const u64 KC3    = bc2(4.166664568298827e-2f);
    const u64 NHALF2 = bc2(-0.5f);
    const u64 ONE2v  = bc2(1.0f);

    u64 qb = fma2(t2, INV2, MAG2);
    unsigned k0 = (unsigned)qb, k1 = (unsigned)(qb >> 32);
    u64 q  = add2(qb, NMAG2);
    u64 r  = fma2(q, NH2, t2);
    r      = fma2(q, PLO2, r);
    u64 s2 = mul2(r, r);
    u64 ps = fma2(s2, KS1, KS2);
    ps     = fma2(ps, s2, KS3);
    u64 sr = fma2(ps, mul2(s2, r), r);
    u64 pc = fma2(s2, KC1, KC2);
    pc     = fma2(pc, s2, KC3);
    pc     = fma2(pc, s2, NHALF2);
    u64 cr = fma2(pc, s2, ONE2v);
    float srl = lo2(sr), srh = hi2(sr), crl = lo2(cr), crh = hi2(cr);
    v[0] = quad_s(k0, srl, crl); v[1] = quad_c(k0, srl, crl);
    v[2] = quad_s(k1, srh, crh); v[3] = quad_c(k1, srh, crh);
}

// ---------------------------------------------------------------------------
// Kernel 1: segment boundaries via neighbor-diff scatter + exact f32 freqs
// ---------------------------------------------------------------------------
__global__ void seg_scatter_kernel(const int* __restrict__ ix) {
    int f = blockIdx.x * blockDim.x + threadIdx.x;
    if (f < NFREQ) {
        double e = (2.0 * (double)(f + 1)) / (double)NFREQ;
        g_freqs[f] = (float)(1.0 / pow(1000.0, e));
    }
    if (f >= NFRAG) return;
    int cur  = ix[f];
    int prev = (f == 0) ? -1 : ix[f - 1];
    for (int s = prev + 1; s <= cur; ++s) g_seg_start[s] = f;
    if (f == NFRAG - 1)
        for (int s = cur + 1; s <= NSEG; ++s) g_seg_start[s] = NFRAG;
}

// ---------------------------------------------------------------------------
// Kernel 2: one block per gene. grid = 500 (SINGLE WAVE at 4 CTA/SM),
// 128 threads. Each warp owns 64-fragment chunks (2 consecutive frags per
// thread -> shared weight LDS + 10 independent FMA chains) and EXITS EARLY
// when its chunk start passes the block's fragment count.
// ---------------------------------------------------------------------------
__global__ __launch_bounds__(NT, 4) void frag_gene_kernel(
    const float2* __restrict__ coords,
    const int*    __restrict__ genes_oi,
    const float*  __restrict__ W1,
    const float*  __restrict__ b1,
    const float*  __restrict__ w2,
    const float*  __restrict__ b2,
    float*        __restrict__ out)
{
    // per-freq chunk: rows [2j, 2j+1, 100+2j, 101+2j], each padded to 12 floats
    __shared__ __align__(16) float Wsh[NFREQ * 48];   // 9600 B
    __shared__ __align__(16) float b1sh[12], w2sh[12];
    __shared__ float frsh[NFREQ];
    __shared__ int   list[MAXF];
    __shared__ float svals[MAXF];
    __shared__ int   cntarr[NT];

    const int g = blockIdx.x;                  // gene slot (whole gene per block)
    const int t = threadIdx.x;
    const int gene = genes_oi[g];

    // Stage per-gene parameters (interleaved chunk layout)
    const float* Wg = W1 + (size_t)gene * (ENC * EDIM);
    #pragma unroll 4
    for (int i = t; i < ENC * EDIM; i += NT) {
        int e = i / EDIM, o = i - e * EDIM;
        int j, slot;
        if (e < 100) { j = e >> 1; slot = e & 1; }
        else         { int e2 = e - 100; j = e2 >> 1; slot = 2 + (e2 & 1); }
        Wsh[j * 48 + slot * 12 + o] = Wg[i];
    }
    if (t < EDIM)  { b1sh[t] = b1[gene * EDIM + t]; w2sh[t] = w2[gene * EDIM + t]; }
    if (t < NFREQ) { frsh[t] = g_freqs[t]; }

    // Cell-pair counts: thread t (<100) owns cells 2t and 2t+1
    int a0 = 0, a1 = 0, c0 = 0, c1 = 0;
    if (t < NCELLS / 2) {
        int s0 = (2 * t)     * NGENES_MB + g;
        int s1 = (2 * t + 1) * NGENES_MB + g;
        a0 = g_seg_start[s0]; c0 = g_seg_start[s0 + 1] - a0;
        a1 = g_seg_start[s1]; c1 = g_seg_start[s1 + 1] - a1;
    }
    int paircnt = c0 + c1;
    cntarr[t] = paircnt;
    __syncthreads();

    // Inclusive Hillis-Steele scan (128 wide) over pair counts
    #pragma unroll
    for (int off = 1; off < NT; off <<= 1) {
        int v = cntarr[t];
        int add = (t >= off) ? cntarr[t - off] : 0;
        __syncthreads();
        cntarr[t] = v + add;
        __syncthreads();
    }
    int total = cntarr[NT - 1];
    int pstart = cntarr[t] - paircnt;          // start of cell 2t's fragments
    for (int i = 0; i < c0; i++) {
        int pos = pstart + i;
        if (pos < MAXF) list[pos] = a0 + i;
    }
    for (int i = 0; i < c1; i++) {
        int pos = pstart + c0 + i;
        if (pos < MAXF) list[pos] = a1 + i;
    }
    __syncthreads();
    if (total > MAXF) total = MAXF;            // statistically unreachable guard

    float w2r[EDIM];
    #pragma unroll
    for (int o = 0; o < EDIM; o++) w2r[o] = w2sh[o];
    const u64 B0 = pk2(b1sh[0], b1sh[1]);
    const u64 B1 = pk2(b1sh[2], b1sh[3]);
    const u64 B2 = pk2(b1sh[4], b1sh[5]);
    const u64 B3 = pk2(b1sh[6], b1sh[7]);
    const u64 B4 = pk2(b1sh[8], b1sh[9]);

    // Main loop: warp widx processes chunks [wb, wb+64); early-exit per warp.
    const int widx = t >> 5;
    const int lane = t & 31;
    const int tmax = (total > 0) ? total - 1 : 0;

    for (int wb = 64 * widx; wb < total; wb += 2 * NT) {
        const int ia = wb + 2 * lane;
        const int ib = ia + 1;
        const bool pa = (ia < total);
        const bool pb = (ib < total);
        const int fa = list[pa ? ia : tmax];
        const int fb = list[pb ? ib : tmax];
        const float2 xya = coords[fa];
        const float2 xyb = coords[fb];
        const u64 xa2 = pk2(xya.x, xya.y);
        const u64 xb2 = pk2(xyb.x, xyb.y);

        u64 a0h = B0, a1h = B1, a2h = B2, a3h = B3, a4h = B4;
        u64 b0h = B0, b1h = B1, b2h = B2, b3h = B3, b4h = B4;

        #pragma unroll 1
        for (int j = 0; j < NFREQ; j++) {
            const u64 fq2 = bc2(frsh[j]);
            float va[4], vb[4];
            sincos2(mul2(xa2, fq2), va);
            sincos2(mul2(xb2, fq2), vb);

            // 4 rows; each row's LDS serves BOTH fragments
            const float* ch = &Wsh[j * 48];
            #pragma unroll
            for (int rr = 0; rr < 4; rr++) {
                const float* rp = ch + rr * 12;
                ulonglong2 ab = *(const ulonglong2*)rp;
                ulonglong2 cd = *(const ulonglong2*)(rp + 4);
                u64 e4 = *(const u64*)(rp + 8);
                const u64 wa = bc2(va[rr]);
                const u64 wb2v = bc2(vb[rr]);
                a0h = fma2(wa, ab.x, a0h);  b0h = fma2(wb2v, ab.x, b0h);
                a1h = fma2(wa, ab.y, a1h);  b1h = fma2(wb2v, ab.y, b1h);
                a2h = fma2(wa, cd.x, a2h);  b2h = fma2(wb2v, cd.x, b2h);
                a3h = fma2(wa, cd.y, a3h);  b3h = fma2(wb2v, cd.y, b3h);
                a4h = fma2(wa, e4, a4h);    b4h = fma2(wb2v, e4, b4h);
            }
        }

        // sigmoid + readout; skip zero readout weights (uniform branch)
        float hva[EDIM] = { lo2(a0h), hi2(a0h), lo2(a1h), hi2(a1h), lo2(a2h),
                            hi2(a2h), lo2(a3h), hi2(a3h), lo2(a4h), hi2(a4h) };
        float hvb[EDIM] = { lo2(b0h), hi2(b0h), lo2(b1h), hi2(b1h), lo2(b2h),
                            hi2(b2h), lo2(b3h), hi2(b3h), lo2(b4h), hi2(b4h) };
        float sa = 0.0f, sb = 0.0f;
        #pragma unroll
        for (int o = 0; o < EDIM; o++) {
            const float w = w2r[o];
            if (w != 0.0f) {                   // w2r uniform across block
                float siga = __fdividef(1.0f, 1.0f + __expf(-hva[o]));
                float sigb = __fdividef(1.0f, 1.0f + __expf(-hvb[o]));
                sa = fmaf(w, siga, sa);
                sb = fmaf(w, sigb, sb);
            }
        }
        if (pa) svals[ia] = sa;
        if (pb) svals[ib] = sb;
    }
    __syncthreads();

    // Deterministic per-cell reduction: thread t owns cells 2t, 2t+1
    if (t < NCELLS / 2) {
        float acc0 = b2[gene];
        for (int i = 0; i < c0; i++) {
            int pos = pstart + i;
            if (pos < MAXF) acc0 += svals[pos];
        }
        out[(2 * t) * NGENES_MB + g] = acc0;
        float acc1 = b2[gene];
        for (int i = 0; i < c1; i++) {
            int pos = pstart + c0 + i;
            if (pos < MAXF) acc1 += svals[pos];
        }
        out[(2 * t + 1) * NGENES_MB + g] = acc1;
    }
}

// ---------------------------------------------------------------------------
// Launch
// Inputs (metadata order): 0 coordinates[F,2] f32, 1 genemapping i32 (unused),
// 2 local_cellxgene_ix i32, 3 genes_oi i32, 4 W1[2000,200,10] f32,
// 5 b1[2000,10] f32, 6 w2[2000,10] f32, 7 b2[2000] f32, (8,9 scalars)
// ---------------------------------------------------------------------------
extern "C" void kernel_launch(void* const* d_in, const int* in_sizes, int n_in,
                              void* d_out, int out_size) {
    const float2* coords   = (const float2*)d_in[0];
    const int*    ix       = (const int*)d_in[2];
    const int*    genes_oi = (const int*)d_in[3];
    const float*  W1       = (const float*)d_in[4];
    const float*  b1       = (const float*)d_in[5];
    const float*  w2       = (const float*)d_in[6];
    const float*  b2       = (const float*)d_in[7];
    float*        out      = (float*)d_out;

    seg_scatter_kernel<<<(NFRAG + 255) / 256, 256>>>(ix);
    frag_gene_kernel<<<NGENES_MB, NT>>>(coords, genes_oi, W1, b1, w2, b2, out);
}

// round 6
// speedup vs baseline: 1.2219x; 1.1457x over previous
#include <cuda_runtime.h>
#include <math.h>

// Problem constants (fixed by the reference setup)
#define NFRAG     131072
#define NCELLS    200
#define NGENES_MB 500
#define NSEG      (NCELLS * NGENES_MB)   // 100000
#define NFREQ     50
#define ENC       200                    // 4 * NFREQ
#define EDIM      10
#define NT        160                    // threads per block (5 warps)
#define NWARP     5
#define MAXF      512                    // max fragments per gene (mean ~262, sd ~16)

typedef unsigned long long u64;

// Scratch (no cudaMalloc allowed)
__device__ int   g_seg_start[NSEG + 1];
__device__ float g_freqs[NFREQ];

// ---------------------------------------------------------------------------
// f32x2 packed helpers (sm_103a FMA pipe)
// ---------------------------------------------------------------------------
__device__ __forceinline__ u64 pk2(float a, float b) {
    u64 d; asm("mov.b64 %0,{%1,%2};" : "=l"(d) : "f"(a), "f"(b)); return d;
}
__device__ __forceinline__ u64 bc2(float a) {
    u64 d; asm("mov.b64 %0,{%1,%1};" : "=l"(d) : "f"(a)); return d;
}
__device__ __forceinline__ u64 fma2(u64 a, u64 b, u64 c) {
    u64 d; asm("fma.rn.f32x2 %0,%1,%2,%3;" : "=l"(d) : "l"(a), "l"(b), "l"(c)); return d;
}
__device__ __forceinline__ u64 mul2(u64 a, u64 b) {
    u64 d; asm("mul.rn.f32x2 %0,%1,%2;" : "=l"(d) : "l"(a), "l"(b)); return d;
}
__device__ __forceinline__ u64 add2(u64 a, u64 b) {
    u64 d; asm("add.rn.f32x2 %0,%1,%2;" : "=l"(d) : "l"(a), "l"(b)); return d;
}
__device__ __forceinline__ float lo2(u64 a) { return __uint_as_float((unsigned)a); }
__device__ __forceinline__ float hi2(u64 a) { return __uint_as_float((unsigned)(a >> 32)); }

// Quadrant fixup: k holds float BITS of (q + 1.5*2^23); low 2 bits == q&3.
__device__ __forceinline__ float quad_s(unsigned k, float sr, float cr) {
    unsigned b = (k & 1u) ? __float_as_uint(cr) : __float_as_uint(sr);
    return __uint_as_float(b ^ ((k & 2u) << 30));
}
__device__ __forceinline__ float quad_c(unsigned k, float sr, float cr) {
    unsigned b = (k & 1u) ? __float_as_uint(sr) : __float_as_uint(cr);
    return __uint_as_float(b ^ (((k + 1u) & 2u) << 30));
}

// Packed sincos: Cody-Waite pi/2 reduction + Cephes minimax polys (FMA pipe).
// v[0]=sin lo, v[1]=cos lo, v[2]=sin hi, v[3]=cos hi.
__device__ __forceinline__ void sincos2(u64 t2, float* v) {
    const u64 INV2   = bc2(0.63661977236758134f);        // 2/pi
    const u64 MAG2   = bc2(12582912.0f);                 // 1.5 * 2^23
    const u64 NMAG2  = bc2(-12582912.0f);
    const u64 NH2    = bc2(-1.57079637050628662109375f); // -pi/2 hi
    const u64 PLO2   = bc2(4.37113900018624283e-8f);     // pi/2 lo correction
    const u64 KS1    = bc2(-1.9515295891e-4f);
    const u64 KS2    = bc2(8.3321608736e-3f);
    const u64 KS3    = bc2(-1.6666654611e-1f);
    const u64 KC1    = bc2(2.443315711809948e-5f);
    const u64 KC2    = bc2(-1.388731625493765e-3f);
    const u64 KC3    = bc2(4.166664568298827e-2f);
    const u64 NHALF2 = bc2(-0.5f);
    const u64 ONE2v  = bc2(1.0f);

    u64 qb = fma2(t2, INV2, MAG2);
    unsigned k0 = (unsigned)qb, k1 = (unsigned)(qb >> 32);
    u64 q  = add2(qb, NMAG2);
    u64 r  = fma2(q, NH2, t2);
    r      = fma2(q, PLO2, r);
    u64 s2 = mul2(r, r);
    u64 ps = fma2(s2, KS1, KS2);
    ps     = fma2(ps, s2, KS3);
    u64 sr = fma2(ps, mul2(s2, r), r);
    u64 pc = fma2(s2, KC1, KC2);
    pc     = fma2(pc, s2, KC3);
    pc     = fma2(pc, s2, NHALF2);
    u64 cr = fma2(pc, s2, ONE2v);
    float srl = lo2(sr), srh = hi2(sr), crl = lo2(cr), crh = hi2(cr);
    v[0] = quad_s(k0, srl, crl); v[1] = quad_c(k0, srl, crl);
    v[2] = quad_s(k1, srh, crh); v[3] = quad_c(k1, srh, crh);
}

// Freq loop over a fragment PAIR with NPC packed accumulators (2*NPC cols),
// SMEM row stride = STRIDE floats (16B-aligned rows).
template<int NPC, int STRIDE>
__device__ __forceinline__ void frag_pair_loop(
    const float* __restrict__ Wsh, const float* __restrict__ frsh,
    u64 xa2, u64 xb2, u64* aacc, u64* bacc)
{
    #pragma unroll 1
    for (int j = 0; j < NFREQ; j++) {
        const u64 fq2 = bc2(frsh[j]);
        float va[4], vb[4];
        sincos2(mul2(xa2, fq2), va);
        sincos2(mul2(xb2, fq2), vb);
        const float* ch = &Wsh[j * 4 * STRIDE];
        #pragma unroll
        for (int rr = 0; rr < 4; rr++) {
            const float* rp = ch + rr * STRIDE;
            u64 w[NPC];
            if constexpr (NPC == 3) {
                ulonglong2 ab = *(const ulonglong2*)rp;
                w[0] = ab.x; w[1] = ab.y; w[2] = *(const u64*)(rp + 4);
            } else {
                ulonglong2 ab = *(const ulonglong2*)rp;
                ulonglong2 cd = *(const ulonglong2*)(rp + 4);
                w[0] = ab.x; w[1] = ab.y; w[2] = cd.x; w[3] = cd.y;
                w[4] = *(const u64*)(rp + 8);
            }
            const u64 wa = bc2(va[rr]);
            const u64 wb = bc2(vb[rr]);
            #pragma unroll
            for (int p = 0; p < NPC; p++) {
                aacc[p] = fma2(wa, w[p], aacc[p]);
                bacc[p] = fma2(wb, w[p], bacc[p]);
            }
        }
    }
}

// ---------------------------------------------------------------------------
// Kernel 1: segment boundaries via neighbor-diff scatter + exact f32 freqs
// ---------------------------------------------------------------------------
__global__ void seg_scatter_kernel(const int* __restrict__ ix) {
    int f = blockIdx.x * blockDim.x + threadIdx.x;
    if (f < NFREQ) {
        double e = (2.0 * (double)(f + 1)) / (double)NFREQ;
        g_freqs[f] = (float)(1.0 / pow(1000.0, e));
    }
    if (f >= NFRAG) return;
    int cur  = ix[f];
    int prev = (f == 0) ? -1 : ix[f - 1];
    for (int s = prev + 1; s <= cur; ++s) g_seg_start[s] = f;
    if (f == NFRAG - 1)
        for (int s = cur + 1; s <= NSEG; ++s) g_seg_start[s] = NFRAG;
}

// ---------------------------------------------------------------------------
// Kernel 2: one block per gene. grid = 500, 160 threads (5 warps), 4 CTA/SM
// -> single wave, 20 warps/SM. Capacity 5*64=320 frags -> every warp does
// <=1 round typically. Data-driven column compaction: only columns with
// w2[gene][o] != 0 are staged/computed (6 in practice); generic 10-col
// fallback otherwise.
// ---------------------------------------------------------------------------
__global__ __launch_bounds__(NT, 4) void frag_gene_kernel(
    const float2* __restrict__ coords,
    const int*    __restrict__ genes_oi,
    const float*  __restrict__ W1,
    const float*  __restrict__ b1,
    const float*  __restrict__ w2,
    const float*  __restrict__ b2,
    float*        __restrict__ out)
{
    __shared__ __align__(16) float Wsh[NFREQ * 48];   // max layout (stride 12)
    __shared__ float frsh[NFREQ];
    __shared__ int   idxsh[8];
    __shared__ float w2csh[8], b1csh[8];
    __shared__ int   nactsh;
    __shared__ int   list[MAXF];
    __shared__ float svals[MAXF];
    __shared__ int   cntarr[NT];

    const int g = blockIdx.x;
    const int t = threadIdx.x;
    const int gene = genes_oi[g];

    if (t == 0) {
        int n = 0;
        for (int o = 0; o < EDIM; o++) {
            float w = w2[gene * EDIM + o];
            if (w != 0.0f && n < 8) {
                idxsh[n] = o;
                w2csh[n] = w;
                b1csh[n] = b1[gene * EDIM + o];
                n++;
            }
        }
        for (int i = n; i < 8; i++) { idxsh[i] = 0; w2csh[i] = 0.0f; b1csh[i] = 0.0f; }
        // count true actives (may exceed 8 -> fallback)
        int full = 0;
        for (int o = 0; o < EDIM; o++) if (w2[gene * EDIM + o] != 0.0f) full++;
        nactsh = full;
    }
    if (t < NFREQ) frsh[t] = g_freqs[t];
    __syncthreads();

    const int  nact    = nactsh;
    const bool compact = (nact <= 6);

    // Stage weights
    const float* Wg = W1 + (size_t)gene * (ENC * EDIM);
    if (compact) {
        // layout: Wsh[j*32 + rr*8 + i] = W[enc_row(j,rr)][idx[i]], i<6; pad 0
        for (int lin = t; lin < NFREQ * 32; lin += NT) {
            int j = lin >> 5, rr = (lin >> 3) & 3, i = lin & 7;
            int e = (rr < 2) ? (2 * j + rr) : (100 + 2 * j + (rr - 2));
            Wsh[lin] = (i < nact) ? Wg[e * EDIM + idxsh[i]] : 0.0f;
        }
    } else {
        // generic layout: stride 12, all 10 cols
        for (int i = t; i < ENC * EDIM; i += NT) {
            int e = i / EDIM, o = i - e * EDIM;
            int j, slot;
            if (e < 100) { j = e >> 1; slot = e & 1; }
            else         { int e2 = e - 100; j = e2 >> 1; slot = 2 + (e2 & 1); }
            Wsh[j * 48 + slot * 12 + o] = Wg[i];
        }
    }

    // Cell-pair counts: thread t (<100) owns cells 2t and 2t+1
    int a0 = 0, a1 = 0, c0 = 0, c1 = 0;
    if (t < NCELLS / 2) {
        int s0 = (2 * t)     * NGENES_MB + g;
        int s1 = (2 * t + 1) * NGENES_MB + g;
        a0 = g_seg_start[s0]; c0 = g_seg_start[s0 + 1] - a0;
        a1 = g_seg_start[s1]; c1 = g_seg_start[s1 + 1] - a1;
    }
    int paircnt = c0 + c1;
    cntarr[t] = paircnt;
    __syncthreads();

    // Inclusive Hillis-Steele scan over pair counts (160 wide)
    #pragma unroll
    for (int off = 1; off < NT; off <<= 1) {
        int v = cntarr[t];
        int add = (t >= off) ? cntarr[t - off] : 0;
        __syncthreads();
        cntarr[t] = v + add;
        __syncthreads();
    }
    int total = cntarr[NT - 1];
    int pstart = cntarr[t] - paircnt;          // start of cell 2t's fragments
    for (int i = 0; i < c0; i++) {
        int pos = pstart + i;
        if (pos < MAXF) list[pos] = a0 + i;
    }
    for (int i = 0; i < c1; i++) {
        int pos = pstart + c0 + i;
        if (pos < MAXF) list[pos] = a1 + i;
    }
    __syncthreads();
    if (total > MAXF) total = MAXF;            // statistically unreachable guard

    // Main loop: warp widx handles chunks [wb, wb+64), stride 320; per-warp
    // early exit. Two consecutive fragments per thread.
    const int widx = t >> 5;
    const int lane = t & 31;
    const int tmax = (total > 0) ? total - 1 : 0;

    for (int wb = 64 * widx; wb < total; wb += 64 * NWARP) {
        const int ia = wb + 2 * lane;
        const int ib = ia + 1;
        const bool pa = (ia < total);
        const bool pb = (ib < total);
        const int fa = list[pa ? ia : tmax];
        const int fb = list[pb ? ib : tmax];
        const float2 xya = coords[fa];
        const float2 xyb = coords[fb];
        const u64 xa2 = pk2(xya.x, xya.y);
        const u64 xb2 = pk2(xyb.x, xyb.y);

        float sa = 0.0f, sb = 0.0f;
        if (compact) {
            u64 aacc[3], bacc[3];
            aacc[0] = bacc[0] = pk2(b1csh[0], b1csh[1]);
            aacc[1] = bacc[1] = pk2(b1csh[2], b1csh[3]);
            aacc[2] = bacc[2] = pk2(b1csh[4], b1csh[5]);
            frag_pair_loop<3, 8>(Wsh, frsh, xa2, xb2, aacc, bacc);

            float hva[6] = { lo2(aacc[0]), hi2(aacc[0]), lo2(aacc[1]),
                             hi2(aacc[1]), lo2(aacc[2]), hi2(aacc[2]) };
            float hvb[6] = { lo2(bacc[0]), hi2(bacc[0]), lo2(bacc[1]),
                             hi2(bacc[1]), lo2(bacc[2]), hi2(bacc[2]) };
            #pragma unroll
            for (int i = 0; i < 6; i++) {
                float w = w2csh[i];   // 0 for padded slots -> exact +0 term
                float siga = __fdividef(1.0f, 1.0f + __expf(-hva[i]));
                float sigb = __fdividef(1.0f, 1.0f + __expf(-hvb[i]));
                sa = fmaf(w, siga, sa);
                sb = fmaf(w, sigb, sb);
            }
        } else {
            u64 aacc[5], bacc[5];
            #pragma unroll
            for (int p = 0; p < 5; p++) {
                u64 bi = pk2(b1[gene * EDIM + 2 * p], b1[gene * EDIM + 2 * p + 1]);
                aacc[p] = bi; bacc[p] = bi;
            }
            frag_pair_loop<5, 12>(Wsh, frsh, xa2, xb2, aacc, bacc);

            #pragma unroll
            for (int p = 0; p < 5; p++) {
                float w0 = w2[gene * EDIM + 2 * p];
                float w1v = w2[gene * EDIM + 2 * p + 1];
                float s0a = __fdividef(1.0f, 1.0f + __expf(-lo2(aacc[p])));
                float s1a = __fdividef(1.0f, 1.0f + __expf(-hi2(aacc[p])));
                float s0b = __fdividef(1.0f, 1.0f + __expf(-lo2(bacc[p])));
                float s1b = __fdividef(1.0f, 1.0f + __expf(-hi2(bacc[p])));
                sa = fmaf(w0, s0a, sa); sa = fmaf(w1v, s1a, sa);
                sb = fmaf(w0, s0b, sb); sb = fmaf(w1v, s1b, sb);
            }
        }
        if (pa) svals[ia] = sa;
        if (pb) svals[ib] = sb;
    }
    __syncthreads();

    // Deterministic per-cell reduction: thread t owns cells 2t, 2t+1
    if (t < NCELLS / 2) {
        float acc0 = b2[gene];
        for (int i = 0; i < c0; i++) {
            int pos = pstart + i;
            if (pos < MAXF) acc0 += svals[pos];
        }
        out[(2 * t) * NGENES_MB + g] = acc0;
        float acc1 = b2[gene];
        for (int i = 0; i < c1; i++) {
            int pos = pstart + c0 + i;
            if (pos < MAXF) acc1 += svals[pos];
        }
        out[(2 * t + 1) * NGENES_MB + g] = acc1;
    }
}

// ---------------------------------------------------------------------------
// Launch
// Inputs (metadata order): 0 coordinates[F,2] f32, 1 genemapping i32 (unused),
// 2 local_cellxgene_ix i32, 3 genes_oi i32, 4 W1[2000,200,10] f32,
// 5 b1[2000,10] f32, 6 w2[2000,10] f32, 7 b2[2000] f32, (8,9 scalars)
// ---------------------------------------------------------------------------
extern "C" void kernel_launch(void* const* d_in, const int* in_sizes, int n_in,
                              void* d_out, int out_size) {
    const float2* coords   = (const float2*)d_in[0];
    const int*    ix       = (const int*)d_in[2];
    const int*    genes_oi = (const int*)d_in[3];
    const float*  W1       = (const float*)d_in[4];
    const float*  b1       = (const float*)d_in[5];
    const float*  w2       = (const float*)d_in[6];
    const float*  b2       = (const float*)d_in[7];
    float*        out      = (float*)d_out;

    seg_scatter_kernel<<<(NFRAG + 255) / 256, 256>>>(ix);
    frag_gene_kernel<<<NGENES_MB, NT>>>(coords, genes_oi, W1, b1, w2, b2, out);
}

// round 7
// speedup vs baseline: 1.2491x; 1.0223x over previous
#include <cuda_runtime.h>
#include <math.h>

// Problem constants (fixed by the reference setup)
#define NFRAG     131072
#define NCELLS    200
#define NGENES_MB 500
#define NSEG      (NCELLS * NGENES_MB)   // 100000
#define NFREQ     50
#define ENC       200                    // 4 * NFREQ
#define EDIM      10
#define NT        160                    // threads per block (5 warps)
#define NWARP     5
#define MAXF      512                    // max fragments per gene (mean ~262, sd ~16)

typedef unsigned long long u64;

// Scratch (no cudaMalloc allowed)
__device__ int   g_seg_start[NSEG + 1];
__device__ float g_freqs[NFREQ];

// ---------------------------------------------------------------------------
// f32x2 packed helpers
// ---------------------------------------------------------------------------
__device__ __forceinline__ u64 pk2(float a, float b) {
    u64 d; asm("mov.b64 %0,{%1,%2};" : "=l"(d) : "f"(a), "f"(b)); return d;
}
__device__ __forceinline__ u64 bc2(float a) {
    u64 d; asm("mov.b64 %0,{%1,%1};" : "=l"(d) : "f"(a)); return d;
}
__device__ __forceinline__ u64 fma2(u64 a, u64 b, u64 c) {
    u64 d; asm("fma.rn.f32x2 %0,%1,%2,%3;" : "=l"(d) : "l"(a), "l"(b), "l"(c)); return d;
}
__device__ __forceinline__ u64 mul2(u64 a, u64 b) {
    u64 d; asm("mul.rn.f32x2 %0,%1,%2;" : "=l"(d) : "l"(a), "l"(b)); return d;
}
__device__ __forceinline__ u64 add2(u64 a, u64 b) {
    u64 d; asm("add.rn.f32x2 %0,%1,%2;" : "=l"(d) : "l"(a), "l"(b)); return d;
}
__device__ __forceinline__ float lo2(u64 a) { return __uint_as_float((unsigned)a); }
__device__ __forceinline__ float hi2(u64 a) { return __uint_as_float((unsigned)(a >> 32)); }

// Quadrant fixup: k holds float BITS of (q + 1.5*2^23); low 2 bits == q&3.
__device__ __forceinline__ float quad_s(unsigned k, float sr, float cr) {
    unsigned b = (k & 1u) ? __float_as_uint(cr) : __float_as_uint(sr);
    return __uint_as_float(b ^ ((k & 2u) << 30));
}
__device__ __forceinline__ float quad_c(unsigned k, float sr, float cr) {
    unsigned b = (k & 1u) ? __float_as_uint(sr) : __float_as_uint(cr);
    return __uint_as_float(b ^ (((k + 1u) & 2u) << 30));
}

// Packed sincos over a (fragA, fragB) angle pair. Outputs PACKED fixed-up
// (sinA,sinB) and (cosA,cosB). Arithmetic per half identical to prior rounds.
__device__ __forceinline__ void sincos2p(u64 t2, u64& s_out, u64& c_out) {
    const u64 INV2   = bc2(0.63661977236758134f);        // 2/pi
    const u64 MAG2   = bc2(12582912.0f);                 // 1.5 * 2^23
    const u64 NMAG2  = bc2(-12582912.0f);
    const u64 NH2    = bc2(-1.57079637050628662109375f); // -pi/2 hi
    const u64 PLO2   = bc2(4.37113900018624283e-8f);     // pi/2 lo correction
    const u64 KS1    = bc2(-1.9515295891e-4f);
    const u64 KS2    = bc2(8.3321608736e-3f);
    const u64 KS3    = bc2(-1.6666654611e-1f);
    const u64 KC1    = bc2(2.443315711809948e-5f);
    const u64 KC2    = bc2(-1.388731625493765e-3f);
    const u64 KC3    = bc2(4.166664568298827e-2f);
    const u64 NHALF2 = bc2(-0.5f);
    const u64 ONE2v  = bc2(1.0f);

    u64 qb = fma2(t2, INV2, MAG2);
    unsigned k0 = (unsigned)qb, k1 = (unsigned)(qb >> 32);
    u64 q  = add2(qb, NMAG2);
    u64 r  = fma2(q, NH2, t2);
    r      = fma2(q, PLO2, r);
    u64 s2 = mul2(r, r);
    u64 ps = fma2(s2, KS1, KS2);
    ps     = fma2(ps, s2, KS3);
    u64 sr = fma2(ps, mul2(s2, r), r);
    u64 pc = fma2(s2, KC1, KC2);
    pc     = fma2(pc, s2, KC3);
    pc     = fma2(pc, s2, NHALF2);
    u64 cr = fma2(pc, s2, ONE2v);
    float srl = lo2(sr), srh = hi2(sr), crl = lo2(cr), crh = hi2(cr);
    s_out = pk2(quad_s(k0, srl, crl), quad_s(k1, srh, crh));
    c_out = pk2(quad_c(k0, srl, crl), quad_c(k1, srh, crh));
}

// ---------------------------------------------------------------------------
// Kernel 1: segment boundaries via neighbor-diff scatter + exact f32 freqs
// ---------------------------------------------------------------------------
__global__ void seg_scatter_kernel(const int* __restrict__ ix) {
    int f = blockIdx.x * blockDim.x + threadIdx.x;
    if (f < NFREQ) {
        double e = (2.0 * (double)(f + 1)) / (double)NFREQ;
        g_freqs[f] = (float)(1.0 / pow(1000.0, e));
    }
    if (f >= NFRAG) return;
    int cur  = ix[f];
    int prev = (f == 0) ? -1 : ix[f - 1];
    for (int s = prev + 1; s <= cur; ++s) g_seg_start[s] = f;
    if (f == NFRAG - 1)
        for (int s = cur + 1; s <= NSEG; ++s) g_seg_start[s] = NFRAG;
}

// ---------------------------------------------------------------------------
// Per-warp main loop. NCOL active output columns; weights pre-broadcast as
// u64 pairs in SMEM (row stride NCOL u64, 16B aligned). Accumulators are
// (fragA, fragB)-packed per column -> NO broadcast MOVs in the loop.
// ---------------------------------------------------------------------------
template<int NCOL>
__device__ __forceinline__ void frag_main(
    const u64* __restrict__ Wsh2, const u64* __restrict__ frsh2,
    const float* __restrict__ w2c, const float* __restrict__ b1c,
    const int* __restrict__ list, float* __restrict__ svals,
    const float2* __restrict__ coords,
    int total, int widx, int lane)
{
    const int tmax = total - 1;
    for (int wb = 64 * widx; wb < total; wb += 64 * NWARP) {
        const int ia = wb + 2 * lane;
        const int ib = ia + 1;
        const bool pa = (ia < total);
        const bool pb = (ib < total);
        const int fa = list[pa ? ia : tmax];
        const int fb = list[pb ? ib : tmax];
        const float2 A = coords[fa];
        const float2 B = coords[fb];
        const u64 xx2 = pk2(A.x, B.x);    // x-coords of both fragments
        const u64 yy2 = pk2(A.y, B.y);    // y-coords of both fragments

        u64 acc[NCOL];
        #pragma unroll
        for (int c = 0; c < NCOL; c++) acc[c] = bc2(b1c[c]);

        #pragma unroll 2
        for (int j = 0; j < NFREQ; j++) {
            const u64 fq2 = frsh2[j];
            u64 sx, cx, sy, cy;
            sincos2p(mul2(xx2, fq2), sx, cx);
            sincos2p(mul2(yy2, fq2), sy, cy);

            const u64* ch = Wsh2 + j * 4 * NCOL;
            u64 v[4] = { sx, cx, sy, cy };
            #pragma unroll
            for (int rr = 0; rr < 4; rr++) {
                const u64* rp = ch + rr * NCOL;
                #pragma unroll
                for (int p = 0; p < NCOL / 2; p++) {
                    ulonglong2 w = *(const ulonglong2*)(rp + 2 * p);
                    acc[2 * p]     = fma2(v[rr], w.x, acc[2 * p]);
                    acc[2 * p + 1] = fma2(v[rr], w.y, acc[2 * p + 1]);
                }
            }
        }

        // sigmoid + readout per half
        float sa = 0.0f, sb = 0.0f;
        #pragma unroll
        for (int c = 0; c < NCOL; c++) {
            const float w = w2c[c];       // 0 for padded slots -> exact +0
            float siga = __fdividef(1.0f, 1.0f + __expf(-lo2(acc[c])));
            float sigb = __fdividef(1.0f, 1.0f + __expf(-hi2(acc[c])));
            sa = fmaf(w, siga, sa);
            sb = fmaf(w, sigb, sb);
        }
        if (pa & pb)      *(float2*)(svals + ia) = make_float2(sa, sb);
        else if (pa)      svals[ia] = sa;
    }
}

// ---------------------------------------------------------------------------
// Kernel 2: one block per gene. grid = 500, 160 threads (5 warps), 4 CTA/SM
// -> single wave. Data-driven column compaction (6 active cols in practice;
// generic 10-col fallback). Weights staged as broadcast u64 pairs.
// ---------------------------------------------------------------------------
__global__ __launch_bounds__(NT, 4) void frag_gene_kernel(
    const float2* __restrict__ coords,
    const int*    __restrict__ genes_oi,
    const float*  __restrict__ W1,
    const float*  __restrict__ b1,
    const float*  __restrict__ w2,
    const float*  __restrict__ b2,
    float*        __restrict__ out)
{
    __shared__ __align__(16) u64 Wsh2[NFREQ * 4 * 10];   // 16000 B worst case
    __shared__ u64   frsh2[NFREQ];
    __shared__ int   idxsh[10];
    __shared__ float w2csh[10], b1csh[10];
    __shared__ int   nactsh;
    __shared__ int   list[MAXF];
    __shared__ __align__(8) float svals[MAXF];
    __shared__ int   warpsum[NWARP];

    const int g = blockIdx.x;
    const int t = threadIdx.x;
    const int widx = t >> 5;
    const int lane = t & 31;
    const int gene = genes_oi[g];

    if (t == 0) {
        int full = 0;
        for (int o = 0; o < EDIM; o++) if (w2[gene * EDIM + o] != 0.0f) full++;
        if (full <= 6) {
            int n = 0;
            for (int o = 0; o < EDIM; o++) {
                float w = w2[gene * EDIM + o];
                if (w != 0.0f) {
                    idxsh[n] = o; w2csh[n] = w; b1csh[n] = b1[gene * EDIM + o];
                    n++;
                }
            }
            for (int i = n; i < 6; i++) { idxsh[i] = 0; w2csh[i] = 0.0f; b1csh[i] = 0.0f; }
            nactsh = 6;
        } else {
            for (int o = 0; o < EDIM; o++) {
                idxsh[o] = o; w2csh[o] = w2[gene * EDIM + o];
                b1csh[o] = b1[gene * EDIM + o];
            }
            nactsh = 10;
        }
    }
    if (t < NFREQ) {
        float fr = g_freqs[t];
        frsh2[t] = pk2(fr, fr);
    }
    __syncthreads();

    const int ncol = nactsh;
    const float* Wg = W1 + (size_t)gene * (ENC * EDIM);

    // Stage weights as broadcast u64 pairs: Wsh2[j*4*ncol + rr*ncol + i]
    if (ncol == 6) {
        for (int lin = t; lin < NFREQ * 24; lin += NT) {
            int j = lin / 24, rem = lin - j * 24;
            int rr = rem / 6, i = rem - rr * 6;
            int e = (rr < 2) ? (2 * j + rr) : (100 + 2 * j + (rr - 2));
            float w = (w2csh[i] != 0.0f || b1csh[i] != 0.0f || i < 6)
                      ? Wg[e * EDIM + idxsh[i]] : 0.0f;
            // padded slots point at col 0 but their w2 is 0 and b1 is 0; the
            // weight value itself is harmless, but zero it for exactness:
            if (i >= 6) w = 0.0f;
            Wsh2[lin] = pk2(w, w);
        }
    } else {
        for (int lin = t; lin < NFREQ * 40; lin += NT) {
            int j = lin / 40, rem = lin - j * 40;
            int rr = rem / 10, i = rem - rr * 10;
            int e = (rr < 2) ? (2 * j + rr) : (100 + 2 * j + (rr - 2));
            float w = Wg[e * EDIM + i];
            Wsh2[lin] = pk2(w, w);
        }
    }

    // NOTE: padded compact slots (i >= actual active count) must contribute 0
    // to svals: their w2csh is 0, so the readout term is exactly +0 even
    // though the dot accumulates real W values for idxsh[i]=0. Correct.

    // Per-cell segment ranges: thread t (<100) owns cells 2t, 2t+1
    int a0 = 0, a1 = 0, c0 = 0, c1 = 0;
    if (t < NCELLS / 2) {
        int s0 = (2 * t)     * NGENES_MB + g;
        int s1 = (2 * t + 1) * NGENES_MB + g;
        a0 = g_seg_start[s0]; c0 = g_seg_start[s0 + 1] - a0;
        a1 = g_seg_start[s1]; c1 = g_seg_start[s1 + 1] - a1;
    }
    const int paircnt = c0 + c1;

    // Warp-shuffle inclusive scan + cross-warp combine (3 barriers total)
    int v = paircnt;
    #pragma unroll
    for (int off = 1; off < 32; off <<= 1) {
        int n = __shfl_up_sync(0xffffffffu, v, off);
        if (lane >= off) v += n;
    }
    if (lane == 31) warpsum[widx] = v;
    __syncthreads();
    int woff = 0, total = 0;
    #pragma unroll
    for (int w = 0; w < NWARP; w++) {
        int ws = warpsum[w];
        if (w < widx) woff += ws;
        total += ws;
    }
    const int pstart = woff + v - paircnt;

    for (int i = 0; i < c0; i++) {
        int pos = pstart + i;
        if (pos < MAXF) list[pos] = a0 + i;
    }
    for (int i = 0; i < c1; i++) {
        int pos = pstart + c0 + i;
        if (pos < MAXF) list[pos] = a1 + i;
    }
    __syncthreads();
    if (total > MAXF) total = MAXF;   // statistically unreachable guard

    if (ncol == 6)
        frag_main<6>(Wsh2, frsh2, w2csh, b1csh, list, svals, coords, total, widx, lane);
    else
        frag_main<10>(Wsh2, frsh2, w2csh, b1csh, list, svals, coords, total, widx, lane);
    __syncthreads();

    // Deterministic per-cell reduction: thread t owns cells 2t, 2t+1
    if (t < NCELLS / 2) {
        float acc0 = b2[gene];
        for (int i = 0; i < c0; i++) {
            int pos = pstart + i;
            if (pos < MAXF) acc0 += svals[pos];
        }
        out[(2 * t) * NGENES_MB + g] = acc0;
        float acc1 = b2[gene];
        for (int i = 0; i < c1; i++) {
            int pos = pstart + c0 + i;
            if (pos < MAXF) acc1 += svals[pos];
        }
        out[(2 * t + 1) * NGENES_MB + g] = acc1;
    }
}

// ---------------------------------------------------------------------------
// Launch
// Inputs (metadata order): 0 coordinates[F,2] f32, 1 genemapping i32 (unused),
// 2 local_cellxgene_ix i32, 3 genes_oi i32, 4 W1[2000,200,10] f32,
// 5 b1[2000,10] f32, 6 w2[2000,10] f32, 7 b2[2000] f32, (8,9 scalars)
// ---------------------------------------------------------------------------
extern "C" void kernel_launch(void* const* d_in, const int* in_sizes, int n_in,
                              void* d_out, int out_size) {
    const float2* coords   = (const float2*)d_in[0];
    const int*    ix       = (const int*)d_in[2];
    const int*    genes_oi = (const int*)d_in[3];
    const float*  W1       = (const float*)d_in[4];
    const float*  b1       = (const float*)d_in[5];
    const float*  w2       = (const float*)d_in[6];
    const float*  b2       = (const float*)d_in[7];
    float*        out      = (float*)d_out;

    seg_scatter_kernel<<<(NFRAG + 255) / 256, 256>>>(ix);
    frag_gene_kernel<<<NGENES_MB, NT>>>(coords, genes_oi, W1, b1, w2, b2, out);
}